// round 8
// baseline (speedup 1.0000x reference)
#include <cuda_runtime.h>
#include <math.h>

// Problem constants
#define BB 256   // batch
#define TT 512   // time steps
#define DD 64    // input dim (layer 0)
#define HH 256   // hidden dim
#define G4H 1024 // 4*H

#define NBLK 128     // persistent grid size (<= 148 SMs, 1 block/SM)
#define RTHREADS 128 // threads per persistent block

// ---------------- scratch (__device__ globals; no allocations allowed) ----------
__device__ float    g_xproj[(size_t)TT * BB * G4H]; // 512 MB: x @ W_ih^T + bias, [T][B][4H]
__device__ float    g_h0seq[(size_t)TT * BB * HH];  // 128 MB: layer-0 output sequence [T][B][H]
__device__ float    g_hbuf[2][BB * HH];             // ping-pong h state
__device__ unsigned g_ctr[2];                       // grid-barrier counters (one per layer)

// ---------------- packed fp32x2 helpers (Blackwell FFMA2 via PTX) ---------------
__device__ __forceinline__ unsigned long long pack2(float lo, float hi) {
    unsigned long long r;
    asm("mov.b64 %0, {%1, %2};" : "=l"(r) : "f"(lo), "f"(hi));
    return r;
}
__device__ __forceinline__ void unpack2(unsigned long long v, float& lo, float& hi) {
    asm("mov.b64 {%0, %1}, %2;" : "=f"(lo), "=f"(hi) : "l"(v));
}
__device__ __forceinline__ void fma2(unsigned long long& d,
                                     unsigned long long a, unsigned long long b) {
    asm("fma.rn.f32x2 %0, %1, %2, %0;" : "+l"(d) : "l"(a), "l"(b));
}

__device__ __forceinline__ float sigf(float x) { return 1.0f / (1.0f + expf(-x)); }

// ================================================================================
// Input-projection GEMM: out[m][gc] = sum_k A[m][k] * W[gc][k] + b_ih[gc] + b_hh[gc]
// m = t*BB + b (xproj layout [T][B][4H]). L0: A = x[b][t][d]; else A = g_h0seq[m][k].
// Block tile 64 m x 128 n, 256 threads, thread tile 4x8 (4 float2 col-pairs), f32x2.
// ================================================================================
template<int K, bool L0>
__global__ __launch_bounds__(256)
void xproj_gemm(const float* __restrict__ A,
                const float* __restrict__ W,
                const float* __restrict__ bih,
                const float* __restrict__ bhh,
                float* __restrict__ out)
{
    __shared__ float At[32 * 65];    // [k][row], padded
    __shared__ float Wt[32 * 130];   // [k][col], even pad (8B-aligned rows)

    const int tid = threadIdx.x;
    const int tx  = tid & 15;        // col-pair lane: cols 2tx + 32j
    const int ty  = tid >> 4;        // rows ty + 16r
    const int m0  = blockIdx.x * 64;
    const int n0  = blockIdx.y * 128;

    unsigned long long acc[4][4];
#pragma unroll
    for (int r = 0; r < 4; r++)
#pragma unroll
        for (int j = 0; j < 4; j++) acc[r][j] = 0ull;

    for (int ks = 0; ks < K; ks += 32) {
        // load A slab 64 rows x 32 k (transposed into At)
#pragma unroll
        for (int q = 0; q < 2; q++) {
            int chunk = tid + 256 * q;          // 512 float4 chunks
            int row   = chunk >> 3;
            int kq    = (chunk & 7) << 2;
            int m     = m0 + row;
            const float* ap;
            if (L0) ap = A + (size_t)(m & 255) * (TT * DD) + (size_t)(m >> 8) * DD + ks + kq;
            else    ap = A + (size_t)m * HH + ks + kq;
            float4 v = *reinterpret_cast<const float4*>(ap);
            At[(kq + 0) * 65 + row] = v.x;
            At[(kq + 1) * 65 + row] = v.y;
            At[(kq + 2) * 65 + row] = v.z;
            At[(kq + 3) * 65 + row] = v.w;
        }
        // load W slab 128 cols x 32 k (transposed into Wt)
#pragma unroll
        for (int q = 0; q < 4; q++) {
            int chunk = tid + 256 * q;          // 1024 float4 chunks
            int col   = chunk >> 3;
            int kq    = (chunk & 7) << 2;
            float4 v  = *reinterpret_cast<const float4*>(
                W + (size_t)(n0 + col) * K + ks + kq);
            Wt[(kq + 0) * 130 + col] = v.x;
            Wt[(kq + 1) * 130 + col] = v.y;
            Wt[(kq + 2) * 130 + col] = v.z;
            Wt[(kq + 3) * 130 + col] = v.w;
        }
        __syncthreads();

#pragma unroll 8
        for (int k = 0; k < 32; k++) {
            unsigned long long w[4];
#pragma unroll
            for (int j = 0; j < 4; j++)
                w[j] = *reinterpret_cast<const unsigned long long*>(
                    &Wt[k * 130 + 2 * tx + 32 * j]);
#pragma unroll
            for (int r = 0; r < 4; r++) {
                float a = At[k * 65 + ty + 16 * r];
                unsigned long long aa = pack2(a, a);
#pragma unroll
                for (int j = 0; j < 4; j++) fma2(acc[r][j], aa, w[j]);
            }
        }
        __syncthreads();
    }

#pragma unroll
    for (int r = 0; r < 4; r++) {
        int m = m0 + ty + 16 * r;
#pragma unroll
        for (int j = 0; j < 4; j++) {
            int gc = n0 + 2 * tx + 32 * j;
            float lo, hi;
            unpack2(acc[r][j], lo, hi);
            float2 o;
            o.x = lo + bih[gc]     + bhh[gc];
            o.y = hi + bih[gc + 1] + bhh[gc + 1];
            *reinterpret_cast<float2*>(&out[(size_t)m * G4H + gc]) = o;
        }
    }
}

// ================================================================================
// Persistent recurrent kernel: one layer, all 512 steps, software grid barrier.
// 128 blocks (8 hcol-blocks x 16 batch-blocks) x 128 threads.
// Block tile: 16 batch x 32 hcols (x4 gates). W_hh slice resident in SMEM.
// Thread tile: 2 rows x (2 hcols x 4 gates) as f32x2; c state in registers.
// ================================================================================
template<bool STORE_SEQ>
__global__ __launch_bounds__(RTHREADS, 1)
void lstm_persist(const float* __restrict__ Whh, int layer)
{
    extern __shared__ float sm[];
    float* Wt = sm;                    // [256][130]  (k-major, gidx = g*32 + c)
    float* Xs = sm + 256 * 130;        // [256][17]   (k-major h_prev tile)

    const int tid = threadIdx.x;
    const int px  = tid & 15;          // hcol pair: cols 2px, 2px+1
    const int py  = tid >> 4;          // rows py, py+8
    const int cb  = blockIdx.x >> 4;   // hcol block 0..7
    const int bi  = blockIdx.x & 15;   // batch block 0..15
    const int jb  = cb * 32;
    const int bb  = bi * 16;

    unsigned* ctr = &g_ctr[layer];
    unsigned  target = 0;

    // ---- one-time: load W_hh slice transposed into SMEM (128 gidx x 256 k) ----
#pragma unroll 4
    for (int it = 0; it < 64; it++) {
        int idx = it * RTHREADS + tid;       // 8192 float4 chunks
        int r   = idx >> 6;                  // gidx 0..127 (g*32 + c)
        int k4  = (idx & 63) << 2;
        int gcol = (r >> 5) * HH + jb + (r & 31);
        float4 v = *reinterpret_cast<const float4*>(Whh + (size_t)gcol * HH + k4);
        Wt[(k4 + 0) * 130 + r] = v.x;
        Wt[(k4 + 1) * 130 + r] = v.y;
        Wt[(k4 + 2) * 130 + r] = v.z;
        Wt[(k4 + 3) * 130 + r] = v.w;
    }
    // ---- zero h(-1) buffer (g_hbuf[0]) cooperatively ----
    for (int i = blockIdx.x * RTHREADS + tid; i < BB * HH; i += NBLK * RTHREADS)
        g_hbuf[0][i] = 0.f;

    // grid barrier (release Wt is smem/local; release hbuf zeros globally)
    __threadfence();
    __syncthreads();
    if (tid == 0) {
        atomicAdd(ctr, 1u);
        target = NBLK;
        while (*(volatile unsigned*)ctr < target) __nanosleep(32);
        __threadfence();
    }
    __syncthreads();
    target = NBLK;

    float creg[2][2] = {{0.f, 0.f}, {0.f, 0.f}};

    for (int t = 0; t < TT; t++) {
        const float* __restrict__ hprev = g_hbuf[t & 1];
        float* __restrict__ hnext = g_hbuf[(t & 1) ^ 1];

        // prefetch input-projection tile (global, immutable this step)
        const float* xp = g_xproj + ((size_t)t * BB + bb) * G4H;
        float2 xpv[2][4];
#pragma unroll
        for (int r = 0; r < 2; r++) {
            int row = py + 8 * r;
#pragma unroll
            for (int g = 0; g < 4; g++)
                xpv[r][g] = *reinterpret_cast<const float2*>(
                    &xp[(size_t)row * G4H + g * HH + jb + 2 * px]);
        }

        // stage h_prev tile (16 rows x 256 k) transposed into Xs; L2 reads (__ldcg)
        {
            int r  = tid >> 3;             // 0..15
            int kc = (tid & 7) << 5;       // 0,32,...,224
            const float4* hp = reinterpret_cast<const float4*>(
                &hprev[(size_t)(bb + r) * HH + kc]);
#pragma unroll
            for (int q = 0; q < 8; q++) {
                float4 v = __ldcg(hp + q);
                int k = kc + 4 * q;
                Xs[(k + 0) * 17 + r] = v.x;
                Xs[(k + 1) * 17 + r] = v.y;
                Xs[(k + 2) * 17 + r] = v.z;
                Xs[(k + 3) * 17 + r] = v.w;
            }
        }
        __syncthreads();

        unsigned long long acc[2][4];
#pragma unroll
        for (int r = 0; r < 2; r++)
#pragma unroll
            for (int g = 0; g < 4; g++) acc[r][g] = 0ull;

#pragma unroll 8
        for (int k = 0; k < HH; k++) {
            float xa = Xs[k * 17 + py];
            float xb = Xs[k * 17 + py + 8];
            unsigned long long A0 = pack2(xa, xa);
            unsigned long long A1 = pack2(xb, xb);
            const float* wr = &Wt[k * 130 + 2 * px];
#pragma unroll
            for (int g = 0; g < 4; g++) {
                unsigned long long w =
                    *reinterpret_cast<const unsigned long long*>(wr + 32 * g);
                fma2(acc[0][g], A0, w);
                fma2(acc[1][g], A1, w);
            }
        }

        // epilogue: gates -> (h, c) for 2 rows x 2 hcols
#pragma unroll
        for (int r = 0; r < 2; r++) {
            int row = bb + py + 8 * r;
            float gi0, gi1, gf0, gf1, gg0, gg1, go0, go1;
            unpack2(acc[r][0], gi0, gi1);
            unpack2(acc[r][1], gf0, gf1);
            unpack2(acc[r][2], gg0, gg1);
            unpack2(acc[r][3], go0, go1);
            gi0 += xpv[r][0].x; gi1 += xpv[r][0].y;
            gf0 += xpv[r][1].x; gf1 += xpv[r][1].y;
            gg0 += xpv[r][2].x; gg1 += xpv[r][2].y;
            go0 += xpv[r][3].x; go1 += xpv[r][3].y;

            float c0 = sigf(gf0) * creg[r][0] + sigf(gi0) * tanhf(gg0);
            float c1 = sigf(gf1) * creg[r][1] + sigf(gi1) * tanhf(gg1);
            creg[r][0] = c0;
            creg[r][1] = c1;
            float h0 = sigf(go0) * tanhf(c0);
            float h1 = sigf(go1) * tanhf(c1);

            size_t hidx = (size_t)row * HH + jb + 2 * px;
            hnext[hidx]     = h0;
            hnext[hidx + 1] = h1;
            if (STORE_SEQ) {
                g_h0seq[(size_t)t * (BB * HH) + hidx]     = h0;
                g_h0seq[(size_t)t * (BB * HH) + hidx + 1] = h1;
            }
        }

        // ---- grid barrier: publish h, wait for all blocks ----
        __threadfence();
        __syncthreads();
        if (tid == 0) {
            atomicAdd(ctr, 1u);
            unsigned tgt = target + NBLK;
            while (*(volatile unsigned*)ctr < tgt) __nanosleep(32);
            __threadfence();
        }
        __syncthreads();
        target += NBLK;
    }
}

// zero barrier counters (run once per replay, before everything)
__global__ void init_kernel()
{
    if (threadIdx.x < 2) g_ctr[threadIdx.x] = 0u;
}

// out[b] = h_last[b] . fc_w + fc_b. TT even -> final h of layer 1 is in g_hbuf[0].
__global__ void fc_kernel(const float* __restrict__ w,
                          const float* __restrict__ bias,
                          float* __restrict__ out)
{
    int b = blockIdx.x;
    int lane = threadIdx.x;
    const float* h = &g_hbuf[0][(size_t)b * HH];
    float s = 0.f;
    for (int j = lane; j < HH; j += 32) s += h[j] * w[j];
#pragma unroll
    for (int o = 16; o; o >>= 1) s += __shfl_xor_sync(0xffffffffu, s, o);
    if (lane == 0) out[b] = s + bias[0];
}

extern "C" void kernel_launch(void* const* d_in, const int* in_sizes, int n_in,
                              void* d_out, int out_size)
{
    const float* x     = (const float*)d_in[0];
    const float* W_ih0 = (const float*)d_in[1];
    const float* W_hh0 = (const float*)d_in[2];
    const float* b_ih0 = (const float*)d_in[3];
    const float* b_hh0 = (const float*)d_in[4];
    const float* W_ih1 = (const float*)d_in[5];
    const float* W_hh1 = (const float*)d_in[6];
    const float* b_ih1 = (const float*)d_in[7];
    const float* b_hh1 = (const float*)d_in[8];
    const float* fc_w  = (const float*)d_in[9];
    const float* fc_b  = (const float*)d_in[10];
    float* out = (float*)d_out;
    (void)in_sizes; (void)n_in; (void)out_size;

    const int rsmem = (256 * 130 + 256 * 17) * sizeof(float);  // 150,528 B
    static bool attr_done = false;
    if (!attr_done) {
        cudaFuncSetAttribute(lstm_persist<true>,
                             cudaFuncAttributeMaxDynamicSharedMemorySize, rsmem);
        cudaFuncSetAttribute(lstm_persist<false>,
                             cudaFuncAttributeMaxDynamicSharedMemorySize, rsmem);
        attr_done = true;
    }

    float* xproj_ptr = nullptr;
    cudaGetSymbolAddress((void**)&xproj_ptr, g_xproj);
    float* h0seq_ptr = nullptr;
    cudaGetSymbolAddress((void**)&h0seq_ptr, g_h0seq);

    init_kernel<<<1, 32>>>();

    dim3 ggrid(TT * BB / 64, G4H / 128);  // (2048, 8)

    // layer 0: input projection (time-parallel), then recurrence
    xproj_gemm<DD, true><<<ggrid, 256>>>(x, W_ih0, b_ih0, b_hh0, xproj_ptr);
    lstm_persist<true><<<NBLK, RTHREADS, rsmem>>>(W_hh0, 0);

    // layer 1: input projection from layer-0 sequence, then recurrence
    xproj_gemm<HH, false><<<ggrid, 256>>>(h0seq_ptr, W_ih1, b_ih1, b_hh1, xproj_ptr);
    lstm_persist<false><<<NBLK, RTHREADS, rsmem>>>(W_hh1, 1);

    fc_kernel<<<BB, 32>>>(fc_w, fc_b, out);
}

// round 9
// speedup vs baseline: 1.3085x; 1.3085x over previous
#include <cuda_runtime.h>
#include <math.h>

// Problem constants
#define BB 256   // batch
#define TT 512   // time steps
#define DD 64    // input dim (layer 0)
#define HH 256   // hidden dim
#define G4H 1024 // 4*H

#define NBLK 128     // persistent grid size (<= 148 SMs, 1 block/SM)
#define RTHREADS 128 // threads per persistent block

typedef unsigned long long ull;

// ---------------- scratch (__device__ globals; no allocations allowed) ----------
__device__ float    g_xproj[(size_t)TT * BB * G4H]; // 512 MB: x @ W_ih^T + bias, [T][B][4H]
__device__ float    g_h0T[(size_t)TT * HH * BB];    // 128 MB: layer-0 outputs TRANSPOSED [T][H][B]
__device__ float    g_hT[2][HH * BB];               // ping-pong h state, TRANSPOSED [H][B]
__device__ unsigned g_ctr[2];                       // grid-barrier counters (one per layer)

// ---------------- packed fp32x2 helpers (Blackwell FFMA2 via PTX) ---------------
__device__ __forceinline__ ull pack2(float lo, float hi) {
    ull r;
    asm("mov.b64 %0, {%1, %2};" : "=l"(r) : "f"(lo), "f"(hi));
    return r;
}
__device__ __forceinline__ void unpack2(ull v, float& lo, float& hi) {
    asm("mov.b64 {%0, %1}, %2;" : "=f"(lo), "=f"(hi) : "l"(v));
}
__device__ __forceinline__ void fma2(ull& d, ull a, ull b) {
    asm("fma.rn.f32x2 %0, %1, %2, %0;" : "+l"(d) : "l"(a), "l"(b));
}

// ---------------- fast activations (MUFU-based, ~1e-6 rel err) ------------------
__device__ __forceinline__ float sigf(float x) {
    return __fdividef(1.0f, 1.0f + __expf(-x));
}
__device__ __forceinline__ float tanf_fast(float x) {
    return __fdividef(2.0f, 1.0f + __expf(-2.0f * x)) - 1.0f;
}

// ---------------- grid barrier primitives ---------------------------------------
__device__ __forceinline__ void bar_red(unsigned* ctr) {
    asm volatile("red.release.gpu.add.u32 [%0], 1;" :: "l"(ctr) : "memory");
}
__device__ __forceinline__ unsigned ld_acq(const unsigned* p) {
    unsigned v;
    asm volatile("ld.acquire.gpu.u32 %0, [%1];" : "=r"(v) : "l"(p) : "memory");
    return v;
}

// ================================================================================
// Input-projection GEMM: out[m][gc] = sum_k A[m][k] * W[gc][k] + b_ih[gc] + b_hh[gc]
// m = t*BB + b (xproj layout [T][B][4H]).
// AMODE 0: A = x, layout [B][T][D].  AMODE 1: A = g_h0T, layout [T][H][B] (transposed).
// Block tile 64 m x 128 n, 256 threads, thread tile 4x8 (4 float2 col-pairs), f32x2.
// ================================================================================
template<int K, int AMODE>
__global__ __launch_bounds__(256)
void xproj_gemm(const float* __restrict__ A,
                const float* __restrict__ W,
                const float* __restrict__ bih,
                const float* __restrict__ bhh,
                float* __restrict__ out)
{
    __shared__ float At[32 * 68];    // [k][row], padded (68*4 % 16 == 0)
    __shared__ float Wt[32 * 130];   // [k][col], even pad (8B-aligned rows)

    const int tid = threadIdx.x;
    const int tx  = tid & 15;        // col-pair lane: cols 2tx + 32j
    const int ty  = tid >> 4;        // rows ty + 16r
    const int m0  = blockIdx.x * 64;
    const int n0  = blockIdx.y * 128;

    ull acc[4][4];
#pragma unroll
    for (int r = 0; r < 4; r++)
#pragma unroll
        for (int j = 0; j < 4; j++) acc[r][j] = 0ull;

    for (int ks = 0; ks < K; ks += 32) {
        // load A slab: 64 rows x 32 k into At[k][row]
        if (AMODE == 0) {
#pragma unroll
            for (int q = 0; q < 2; q++) {
                int chunk = tid + 256 * q;          // 512 float4 chunks
                int row   = chunk >> 3;
                int kq    = (chunk & 7) << 2;
                int m     = m0 + row;
                const float* ap = A + (size_t)(m & 255) * (TT * DD)
                                    + (size_t)(m >> 8) * DD + ks + kq;
                float4 v = *reinterpret_cast<const float4*>(ap);
                At[(kq + 0) * 68 + row] = v.x;
                At[(kq + 1) * 68 + row] = v.y;
                At[(kq + 2) * 68 + row] = v.z;
                At[(kq + 3) * 68 + row] = v.w;
            }
        } else {
            // h0T[t][k][b]: rows of At load directly (no transpose)
            int t  = m0 >> 8;
            int b0 = m0 & 255;
#pragma unroll
            for (int q = 0; q < 2; q++) {
                int chunk = tid + 256 * q;          // 512 float4 chunks
                int k  = chunk >> 4;                // 0..31
                int b4 = (chunk & 15) << 2;
                float4 v = *reinterpret_cast<const float4*>(
                    A + ((size_t)t * HH + ks + k) * BB + b0 + b4);
                *reinterpret_cast<float4*>(&At[k * 68 + b4]) = v;
            }
        }
        // load W slab 128 cols x 32 k (transposed into Wt)
#pragma unroll
        for (int q = 0; q < 4; q++) {
            int chunk = tid + 256 * q;              // 1024 float4 chunks
            int col   = chunk >> 3;
            int kq    = (chunk & 7) << 2;
            float4 v  = *reinterpret_cast<const float4*>(
                W + (size_t)(n0 + col) * K + ks + kq);
            Wt[(kq + 0) * 130 + col] = v.x;
            Wt[(kq + 1) * 130 + col] = v.y;
            Wt[(kq + 2) * 130 + col] = v.z;
            Wt[(kq + 3) * 130 + col] = v.w;
        }
        __syncthreads();

#pragma unroll 8
        for (int k = 0; k < 32; k++) {
            ull w[4];
#pragma unroll
            for (int j = 0; j < 4; j++)
                w[j] = *reinterpret_cast<const ull*>(
                    &Wt[k * 130 + 2 * tx + 32 * j]);
#pragma unroll
            for (int r = 0; r < 4; r++) {
                float a = At[k * 68 + ty + 16 * r];
                ull aa = pack2(a, a);
#pragma unroll
                for (int j = 0; j < 4; j++) fma2(acc[r][j], aa, w[j]);
            }
        }
        __syncthreads();
    }

#pragma unroll
    for (int r = 0; r < 4; r++) {
        int m = m0 + ty + 16 * r;
#pragma unroll
        for (int j = 0; j < 4; j++) {
            int gc = n0 + 2 * tx + 32 * j;
            float lo, hi;
            unpack2(acc[r][j], lo, hi);
            float2 o;
            o.x = lo + bih[gc]     + bhh[gc];
            o.y = hi + bih[gc + 1] + bhh[gc + 1];
            *reinterpret_cast<float2*>(&out[(size_t)m * G4H + gc]) = o;
        }
    }
}

// ================================================================================
// Persistent recurrent kernel: one layer, all 512 steps, software grid barrier.
// 128 blocks (8 hcol-blocks x 16 batch-blocks) x 128 threads.
// Block tile: 16 batch x 32 hcols (x4 gates). W_hh slice resident in SMEM.
// Warp w = gate w (dedups W smem reads). Lane: c2 = lane&15 (hcol pair),
// rh = lane>>4 (row-half). Thread computes 8 rows (4 packed pairs) x 2 hcols
// of gate w via f32x2; gates exchanged through a small SMEM tile for the
// pointwise epilogue. h state exchanged TRANSPOSED [H][B] via L2.
// ================================================================================
template<bool STORE_SEQ>
__global__ __launch_bounds__(RTHREADS, 1)
void lstm_persist(const float* __restrict__ Whh, int layer)
{
    extern __shared__ float sm[];
    float* Wt = sm;                      // [256][130]  k-major, gidx = g*32 + c
    float* Xs = Wt + 256 * 130;          // [256][20]   k-major h_prev tile [k][b]
    float* Gs = Xs + 256 * 20;           // [4*32][20]  gate exchange [gatecol][b]

    const int tid = threadIdx.x;
    const int gw  = tid >> 5;            // warp = gate 0..3
    const int lane = tid & 31;
    const int c2  = lane & 15;           // hcol pair: cols 2c2, 2c2+1
    const int rh  = lane >> 4;           // row half: rows 8rh..8rh+7
    const int cb  = blockIdx.x >> 4;     // hcol block 0..7
    const int bi  = blockIdx.x & 15;     // batch block 0..15
    const int jb  = cb * 32;
    const int bb  = bi * 16;

    unsigned* ctr = &g_ctr[layer];
    unsigned  target = NBLK;

    // ---- one-time: load W_hh slice transposed into SMEM (128 gidx x 256 k) ----
#pragma unroll 4
    for (int it = 0; it < 64; it++) {
        int idx = it * RTHREADS + tid;       // 8192 float4 chunks
        int r   = idx >> 6;                  // gidx 0..127 (g*32 + c)
        int k4  = (idx & 63) << 2;
        int gcol = (r >> 5) * HH + jb + (r & 31);
        float4 v = *reinterpret_cast<const float4*>(Whh + (size_t)gcol * HH + k4);
        Wt[(k4 + 0) * 130 + r] = v.x;
        Wt[(k4 + 1) * 130 + r] = v.y;
        Wt[(k4 + 2) * 130 + r] = v.z;
        Wt[(k4 + 3) * 130 + r] = v.w;
    }
    // ---- zero h(-1) buffer (g_hT[0]) cooperatively ----
    for (int i = blockIdx.x * RTHREADS + tid; i < BB * HH; i += NBLK * RTHREADS)
        g_hT[0][i] = 0.f;

    // initial arrive (publishes hT zeros; Wt covered by barrier's syncthreads)
    __syncthreads();
    if (tid == 0) { __threadfence(); bar_red(ctr); }

    // epilogue item owned by this thread: hcol j (0..31), batch quad bq (0..3)
    const int j  = tid & 31;
    const int bq = tid >> 5;
    float creg[4] = {0.f, 0.f, 0.f, 0.f};

    // prefetch xproj tile for t=0
    float xq[4][4];
    {
        const float* xb = g_xproj + ((size_t)0 * BB + bb + 4 * bq) * G4H + jb + j;
#pragma unroll
        for (int g = 0; g < 4; g++)
#pragma unroll
            for (int b = 0; b < 4; b++)
                xq[g][b] = __ldcg(xb + (size_t)b * G4H + g * HH);
    }

    for (int t = 0; t < TT; t++) {
        // ---- wait: all blocks published h(t-1) ----
        while (ld_acq(ctr) < target) {}
        target += NBLK;

        const float* __restrict__ hprev = g_hT[t & 1];
        float* __restrict__ hnext = g_hT[(t & 1) ^ 1];

        // ---- stage h_prev tile [256 k][16 b] into Xs (pure float4, no transpose)
#pragma unroll
        for (int q = 0; q < 8; q++) {
            int chunk = q * RTHREADS + tid;      // 1024 chunks
            int k  = chunk >> 2;
            int c4 = (chunk & 3) << 2;
            float4 v = __ldcg(reinterpret_cast<const float4*>(
                hprev + (size_t)k * BB + bb + c4));
            *reinterpret_cast<float4*>(&Xs[k * 20 + c4]) = v;
        }
        __syncthreads();

        // ---- inner GEMM: gate gw, 8 rows (4 pairs) x 2 hcols per thread ----
        ull acc[4][2];
#pragma unroll
        for (int p = 0; p < 4; p++) { acc[p][0] = 0ull; acc[p][1] = 0ull; }

#pragma unroll 8
        for (int k = 0; k < HH; k++) {
            const float* xr = &Xs[k * 20 + 8 * rh];
            ull A0 = *reinterpret_cast<const ull*>(xr + 0);
            ull A1 = *reinterpret_cast<const ull*>(xr + 2);
            ull A2 = *reinterpret_cast<const ull*>(xr + 4);
            ull A3 = *reinterpret_cast<const ull*>(xr + 6);
            float2 wv = *reinterpret_cast<const float2*>(
                &Wt[k * 130 + gw * 32 + 2 * c2]);
            ull W0 = pack2(wv.x, wv.x);
            ull W1 = pack2(wv.y, wv.y);
            fma2(acc[0][0], A0, W0); fma2(acc[0][1], A0, W1);
            fma2(acc[1][0], A1, W0); fma2(acc[1][1], A1, W1);
            fma2(acc[2][0], A2, W0); fma2(acc[2][1], A2, W1);
            fma2(acc[3][0], A3, W0); fma2(acc[3][1], A3, W1);
        }

        // ---- gate exchange through SMEM: Gs[g*32 + col][b] ----
#pragma unroll
        for (int p = 0; p < 4; p++) {
            *reinterpret_cast<ull*>(
                &Gs[(gw * 32 + 2 * c2    ) * 20 + 8 * rh + 2 * p]) = acc[p][0];
            *reinterpret_cast<ull*>(
                &Gs[(gw * 32 + 2 * c2 + 1) * 20 + 8 * rh + 2 * p]) = acc[p][1];
        }
        __syncthreads();

        // ---- epilogue: thread owns (hcol j, batch quad bq) ----
        float4 vi = *reinterpret_cast<const float4*>(&Gs[(0 * 32 + j) * 20 + 4 * bq]);
        float4 vf = *reinterpret_cast<const float4*>(&Gs[(1 * 32 + j) * 20 + 4 * bq]);
        float4 vg = *reinterpret_cast<const float4*>(&Gs[(2 * 32 + j) * 20 + 4 * bq]);
        float4 vo = *reinterpret_cast<const float4*>(&Gs[(3 * 32 + j) * 20 + 4 * bq]);

        float gs[4][4];
        gs[0][0] = vi.x + xq[0][0]; gs[0][1] = vi.y + xq[0][1];
        gs[0][2] = vi.z + xq[0][2]; gs[0][3] = vi.w + xq[0][3];
        gs[1][0] = vf.x + xq[1][0]; gs[1][1] = vf.y + xq[1][1];
        gs[1][2] = vf.z + xq[1][2]; gs[1][3] = vf.w + xq[1][3];
        gs[2][0] = vg.x + xq[2][0]; gs[2][1] = vg.y + xq[2][1];
        gs[2][2] = vg.z + xq[2][2]; gs[2][3] = vg.w + xq[2][3];
        gs[3][0] = vo.x + xq[3][0]; gs[3][1] = vo.y + xq[3][1];
        gs[3][2] = vo.z + xq[3][2]; gs[3][3] = vo.w + xq[3][3];

        // prefetch next step's xproj tile (overlaps MUFU chain + barrier)
        if (t + 1 < TT) {
            const float* xb = g_xproj + ((size_t)(t + 1) * BB + bb + 4 * bq) * G4H
                            + jb + j;
#pragma unroll
            for (int g = 0; g < 4; g++)
#pragma unroll
                for (int b = 0; b < 4; b++)
                    xq[g][b] = __ldcg(xb + (size_t)b * G4H + g * HH);
        }

        float hv[4];
#pragma unroll
        for (int b = 0; b < 4; b++) {
            float iv = sigf(gs[0][b]);
            float fv = sigf(gs[1][b]);
            float gv = tanf_fast(gs[2][b]);
            float ov = sigf(gs[3][b]);
            float c  = fv * creg[b] + iv * gv;
            creg[b]  = c;
            hv[b]    = ov * tanf_fast(c);
        }

        float4 hq = make_float4(hv[0], hv[1], hv[2], hv[3]);
        size_t hoff = (size_t)(jb + j) * BB + bb + 4 * bq;
        *reinterpret_cast<float4*>(hnext + hoff) = hq;
        if (STORE_SEQ)
            *reinterpret_cast<float4*>(g_h0T + (size_t)t * (HH * BB) + hoff) = hq;

        // ---- arrive: publish h(t) ----
        __syncthreads();   // also guards Gs/Xs reuse next iteration
        if (tid == 0) { __threadfence(); bar_red(ctr); }
    }
}

// zero barrier counters (run once per replay, before everything)
__global__ void init_kernel()
{
    if (threadIdx.x < 2) g_ctr[threadIdx.x] = 0u;
}

// out[b] = h_last[b] . fc_w + fc_b. TT even -> final h of layer 1 is g_hT[0] ([H][B]).
__global__ void fc_kernel(const float* __restrict__ w,
                          const float* __restrict__ bias,
                          float* __restrict__ out)
{
    int b = threadIdx.x;   // 256 threads, 1 block
    float s = 0.f;
#pragma unroll 8
    for (int j = 0; j < HH; j++)
        s += g_hT[0][(size_t)j * BB + b] * w[j];
    out[b] = s + bias[0];
}

extern "C" void kernel_launch(void* const* d_in, const int* in_sizes, int n_in,
                              void* d_out, int out_size)
{
    const float* x     = (const float*)d_in[0];
    const float* W_ih0 = (const float*)d_in[1];
    const float* W_hh0 = (const float*)d_in[2];
    const float* b_ih0 = (const float*)d_in[3];
    const float* b_hh0 = (const float*)d_in[4];
    const float* W_ih1 = (const float*)d_in[5];
    const float* W_hh1 = (const float*)d_in[6];
    const float* b_ih1 = (const float*)d_in[7];
    const float* b_hh1 = (const float*)d_in[8];
    const float* fc_w  = (const float*)d_in[9];
    const float* fc_b  = (const float*)d_in[10];
    float* out = (float*)d_out;
    (void)in_sizes; (void)n_in; (void)out_size;

    const int rsmem = (256 * 130 + 256 * 20 + 4 * 32 * 20) * sizeof(float); // 163,840 B
    static bool attr_done = false;
    if (!attr_done) {
        cudaFuncSetAttribute(lstm_persist<true>,
                             cudaFuncAttributeMaxDynamicSharedMemorySize, rsmem);
        cudaFuncSetAttribute(lstm_persist<false>,
                             cudaFuncAttributeMaxDynamicSharedMemorySize, rsmem);
        attr_done = true;
    }

    float* xproj_ptr = nullptr;
    cudaGetSymbolAddress((void**)&xproj_ptr, g_xproj);
    float* h0T_ptr = nullptr;
    cudaGetSymbolAddress((void**)&h0T_ptr, g_h0T);

    init_kernel<<<1, 32>>>();

    dim3 ggrid(TT * BB / 64, G4H / 128);  // (2048, 8)

    // layer 0: input projection (time-parallel), then recurrence
    xproj_gemm<DD, 0><<<ggrid, 256>>>(x, W_ih0, b_ih0, b_hh0, xproj_ptr);
    lstm_persist<true><<<NBLK, RTHREADS, rsmem>>>(W_hh0, 0);

    // layer 1: input projection from transposed layer-0 sequence, then recurrence
    xproj_gemm<HH, 1><<<ggrid, 256>>>(h0T_ptr, W_ih1, b_ih1, b_hh1, xproj_ptr);
    lstm_persist<false><<<NBLK, RTHREADS, rsmem>>>(W_hh1, 1);

    fc_kernel<<<1, BB>>>(fc_w, fc_b, out);
}